// round 3
// baseline (speedup 1.0000x reference)
#include <cuda_runtime.h>

// ---------------------------------------------------------------------------
// Inverse DTCWT qshift level, fully fused, barrier-free, row-pair streaming.
//
// Filter algebra (validated in R1/R2, rel_err ~1e-7):
//   10-tap qshift synthesis reduces to 3 nonzero taps per output phase s=n&3
//   over inputs at reflect(2*(n>>2)+off).  F1 is a phase/sign permutation of F0.
//
// R3: rows 2h and 2h+1 share the same 12 subband plane values (6 Yhr + 6 Yhi
//   at identical offsets); which array feeds which row flips with parity.
//   Process row PAIRS: 12 uniform-base coalesced LDGs -> c2q for both rows.
//   128-output-row strips amortize the 5-pair window prologue over 32 steps.
// ---------------------------------------------------------------------------

static constexpr float A0 =  0.0351638365171441f;
static constexpr float A2 = -0.0883294244510729f;
static constexpr float A3c = 0.233890320607236f;
static constexpr float A4 =  0.760272369066126f;
static constexpr float A5 =  0.587518297723561f;
static constexpr float A7 = -0.114301837144249f;
static constexpr float RS2 = 0.70710678118654752440f; // 1/sqrt(2)

// [filter 0/1][phase s][tap]
__constant__ int c_off[2][4][3] = {
    { { 4, 2, 0 }, { 3, 1, -1 }, { 2, 0, -2 }, { 1, -1, -3 } },
    { { 3, 1, -1 }, { 4, 2, 0 }, { 1, -1, -3 }, { 2, 0, -2 } }
};
__constant__ float c_tap[2][4][3] = {
    { { A0, A2, A4 }, { A7, A5, A3c }, { A3c, A5, A7 }, { A4, A2, A0 } },
    { { A7, A5, A3c }, { -A0, -A2, -A4 }, { -A4, -A2, -A0 }, { A3c, A5, A7 } }
};

__device__ __forceinline__ int rf128(int x) {
    return x < 0 ? (-1 - x) : (x > 127 ? (255 - x) : x);
}

#define IW   128
#define HH2  64
#define OW   256
#define PL   4096          // Yh plane elements (64*64)
#define FULLM 0xffffffffu

__global__ __launch_bounds__(128, 6)
void dtcwt_inv_kernel(const float* __restrict__ Yl,
                      const float* __restrict__ Yhr,
                      const float* __restrict__ Yhi,
                      float* __restrict__ out)
{
    const int tid  = threadIdx.x;
    const int lane = tid & 31;
    const int S    = blockIdx.x >> 1;            // strip: output rows [128S,128S+127]
    const int wq   = ((blockIdx.x & 1) << 2) | (tid >> 5); // global warp 0..7 (col group)
    const int g    = blockIdx.y;

    const float* ylg = Yl  + (size_t)g * (IW * IW);
    const float* yhr = Yhr + (size_t)g * (6 * PL);
    const float* yhi = Yhi + (size_t)g * (6 * PL);
    float*       og  = out + (size_t)g * (OW * OW);

    // ---- per-lane constants ------------------------------------------------
    const int col = wq * 32 + lane;
    const int s   = col & 3;

    const float t00 = c_tap[0][s][0], t01 = c_tap[0][s][1], t02 = c_tap[0][s][2];
    const float t10 = c_tap[1][s][0], t11 = c_tap[1][s][1], t12 = c_tap[1][s][2];

    const int lb  = (lane >> 2) << 1;
    const int s00 = lb + c_off[0][s][0] + 3;
    const int s01 = lb + c_off[0][s][1] + 3;
    const int s02 = lb + c_off[0][s][2] + 3;
    const int s10 = lb + c_off[1][s][0] + 3;
    const int s11 = lb + c_off[1][s][1] + 3;
    const int s12 = lb + c_off[1][s][2] + 3;

    const int   x    = rf128(16 * wq - 3 + lane);  // staged input column
    const bool  p    = (x & 1) != 0;               // c2q column parity
    const int   wcp  = x >> 1;                     // Yh column
    const float rs2p = p ? -RS2 : RS2;

    // ---- compute one row PAIR (v = 2h, 2h+1) of y1, y2 ---------------------
    auto cpair = [&](int h, float& y1a, float& y2a, float& y1b, float& y2b) {
        const int yr0 = rf128(2 * h);
        const int yr1 = rf128(2 * h + 1);
        const int hp  = yr0 >> 1;                  // shared Yh row

        const float yl0 = ylg[yr0 * IW + x];
        const float yl1 = ylg[yr1 * IW + x];

        const float* Rb = yhr + hp * HH2 + wcp;    // uniform base per LDG
        const float* Ib = yhi + hp * HH2 + wcp;
        const float R0 = Rb[0],      R5 = Rb[5*PL];
        const float R2v = Rb[2*PL],  R3v = Rb[3*PL];
        const float R1v = Rb[1*PL],  R4v = Rb[4*PL];
        const float I0 = Ib[0],      I5 = Ib[5*PL];
        const float I2v = Ib[2*PL],  I3v = Ib[3*PL];
        const float I1v = Ib[1*PL],  I4v = Ib[4*PL];

        // c2q: band (c1,c2) pairs lh(0,5) hl(2,3) hh(1,4)
        //   q=0 value: p ? RS2*(Ic1+Ic2) : RS2*(Rc1+Rc2)
        //   q=1 value: p ? RS2*(Rc2-Rc1) : RS2*(Ic1-Ic2)  == rs2p*(b1-b2)
        float lhA, lhB, hlA, hlB, hhA, hhB;
        {
            const float a1 = p ? I0 : R0,  a2 = p ? I5 : R5;
            const float b1 = p ? R0 : I0,  b2 = p ? R5 : I5;
            lhA = RS2 * (a1 + a2);  lhB = rs2p * (b1 - b2);
        }
        {
            const float a1 = p ? I2v : R2v,  a2 = p ? I3v : R3v;
            const float b1 = p ? R2v : I2v,  b2 = p ? R3v : I3v;
            hlA = RS2 * (a1 + a2);  hlB = rs2p * (b1 - b2);
        }
        {
            const float a1 = p ? I1v : R1v,  a2 = p ? I4v : R4v;
            const float b1 = p ? R1v : I1v,  b2 = p ? R4v : I4v;
            hhA = RS2 * (a1 + a2);  hhB = rs2p * (b1 - b2);
        }
        if (yr0 & 1) {   // boundary reflection flips pair parity (warp-uniform)
            float t;
            t = lhA; lhA = lhB; lhB = t;
            t = hlA; hlA = hlB; hlB = t;
            t = hhA; hhA = hhB; hhB = t;
        }

        y1a = t00 * __shfl_sync(FULLM, yl0, s00)
            + t01 * __shfl_sync(FULLM, yl0, s01)
            + t02 * __shfl_sync(FULLM, yl0, s02)
            + t10 * __shfl_sync(FULLM, hlA, s10)
            + t11 * __shfl_sync(FULLM, hlA, s11)
            + t12 * __shfl_sync(FULLM, hlA, s12);
        y2a = t00 * __shfl_sync(FULLM, lhA, s00)
            + t01 * __shfl_sync(FULLM, lhA, s01)
            + t02 * __shfl_sync(FULLM, lhA, s02)
            + t10 * __shfl_sync(FULLM, hhA, s10)
            + t11 * __shfl_sync(FULLM, hhA, s11)
            + t12 * __shfl_sync(FULLM, hhA, s12);
        y1b = t00 * __shfl_sync(FULLM, yl1, s00)
            + t01 * __shfl_sync(FULLM, yl1, s01)
            + t02 * __shfl_sync(FULLM, yl1, s02)
            + t10 * __shfl_sync(FULLM, hlB, s10)
            + t11 * __shfl_sync(FULLM, hlB, s11)
            + t12 * __shfl_sync(FULLM, hlB, s12);
        y2b = t00 * __shfl_sync(FULLM, lhB, s00)
            + t01 * __shfl_sync(FULLM, lhB, s01)
            + t02 * __shfl_sync(FULLM, lhB, s02)
            + t10 * __shfl_sync(FULLM, hhB, s10)
            + t11 * __shfl_sync(FULLM, hhB, s11)
            + t12 * __shfl_sync(FULLM, hhB, s12);
    };

    // ---- vertical streaming window: w[j] = y row (2i - 4 + j), j = 0..9 ----
    const int i0 = S * 32;
    float w1[10], w2[10];
#pragma unroll
    for (int k = 0; k < 5; ++k)
        cpair(i0 - 2 + k, w1[2*k], w2[2*k], w1[2*k+1], w2[2*k+1]);

    float* op = og + (size_t)(S * 128) * OW + col;
#pragma unroll 2
    for (int ii = 0; ii < 32; ++ii) {
        const float v0 = A0  * w1[8] + A2  * w1[6] + A4 * w1[4]
                       + A7  * w2[7] + A5  * w2[5] + A3c * w2[3];
        const float v1 = A7  * w1[7] + A5  * w1[5] + A3c * w1[3]
                       - A0  * w2[8] - A2  * w2[6] - A4 * w2[4];
        const float v2 = A3c * w1[6] + A5  * w1[4] + A7 * w1[2]
                       - A4  * w2[5] - A2  * w2[3] - A0 * w2[1];
        const float v3 = A4  * w1[5] + A2  * w1[3] + A0 * w1[1]
                       + A3c * w2[6] + A5  * w2[4] + A7 * w2[2];

        __stcs(op + 0 * OW, v0);
        __stcs(op + 1 * OW, v1);
        __stcs(op + 2 * OW, v2);
        __stcs(op + 3 * OW, v3);
        op += 4 * OW;

        if (ii < 31) {
#pragma unroll
            for (int j = 0; j < 8; ++j) { w1[j] = w1[j + 2]; w2[j] = w2[j + 2]; }
            cpair(i0 + ii + 3, w1[8], w2[8], w1[9], w2[9]);
        }
    }
}

extern "C" void kernel_launch(void* const* d_in, const int* in_sizes, int n_in,
                              void* d_out, int out_size)
{
    const float* Yl  = (const float*)d_in[0];
    const float* Yhr = (const float*)d_in[1];
    const float* Yhi = (const float*)d_in[2];
    float* out = (float*)d_out;

    const int n_img = in_sizes[0] / (IW * IW);   // 512 for (8,64,128,128)

    dim3 grid(4, n_img);   // x: (strip<<1)|col-half, y: image
    dtcwt_inv_kernel<<<grid, 128>>>(Yl, Yhr, Yhi, out);
}

// round 4
// speedup vs baseline: 1.1354x; 1.1354x over previous
#include <cuda_runtime.h>

// ---------------------------------------------------------------------------
// Inverse DTCWT qshift level, fully fused, barrier-free, row-pair streaming.
//
// Filter algebra (validated R1-R3, rel_err ~1e-7):
//   10-tap qshift synthesis reduces to 3 nonzero taps per output phase s=n&3
//   over inputs at reflect(2*(n>>2)+off).  F1 is a phase/sign permutation of F0.
//   Rows 2h,2h+1 share the same 12 subband plane values; parity flips roles.
//
// R4: full-height strips (68 pairs / 256 rows, vs 80 with 64-row strips),
//   RS2 folded into pre-scaled constant taps (yl scaled by sqrt2 at load),
//   c2q as 12 uniform coalesced LDG + 12 ADD + 6 SEL per pair,
//   128-thread CTAs with launch_bounds(128,8) for 50% occupancy.
// ---------------------------------------------------------------------------

static constexpr float A0 =  0.0351638365171441f;
static constexpr float A2 = -0.0883294244510729f;
static constexpr float A3c = 0.233890320607236f;
static constexpr float A4 =  0.760272369066126f;
static constexpr float A5 =  0.587518297723561f;
static constexpr float A7 = -0.114301837144249f;
static constexpr float RS2 = 0.70710678118654752440f; // 1/sqrt(2)
static constexpr float SQ2 = 1.41421356237309504880f;

// [filter 0/1][phase s][tap]  (offsets unchanged from R1-R3)
__constant__ int c_off[2][4][3] = {
    { { 4, 2, 0 }, { 3, 1, -1 }, { 2, 0, -2 }, { 1, -1, -3 } },
    { { 3, 1, -1 }, { 4, 2, 0 }, { 1, -1, -3 }, { 2, 0, -2 } }
};
// taps pre-scaled by RS2 (c2q scale folded in; yl path compensated by SQ2)
__constant__ float c_t0r[4][3] = {
    { A0*RS2, A2*RS2, A4*RS2 }, { A7*RS2, A5*RS2, A3c*RS2 },
    { A3c*RS2, A5*RS2, A7*RS2 }, { A4*RS2, A2*RS2, A0*RS2 }
};
__constant__ float c_t1r[4][3] = {
    { A7*RS2, A5*RS2, A3c*RS2 }, { -A0*RS2, -A2*RS2, -A4*RS2 },
    { -A4*RS2, -A2*RS2, -A0*RS2 }, { A3c*RS2, A5*RS2, A7*RS2 }
};

__device__ __forceinline__ int rf128(int x) {
    return x < 0 ? (-1 - x) : (x > 127 ? (255 - x) : x);
}

#define IW   128
#define HH2  64
#define OW   256
#define PL   4096
#define FULLM 0xffffffffu

__global__ __launch_bounds__(128, 8)
void dtcwt_inv_kernel(const float* __restrict__ Yl,
                      const float* __restrict__ Yhr,
                      const float* __restrict__ Yhi,
                      float* __restrict__ out)
{
    const int tid  = threadIdx.x;
    const int lane = tid & 31;
    const int wq   = (blockIdx.x << 2) | (tid >> 5);  // col group 0..7
    const int g    = blockIdx.y;

    const float* ylg = Yl  + (size_t)g * (IW * IW);
    const float* yhr = Yhr + (size_t)g * (6 * PL);
    const float* yhi = Yhi + (size_t)g * (6 * PL);
    float*       og  = out + (size_t)g * (OW * OW);

    // ---- per-lane constants ------------------------------------------------
    const int col = wq * 32 + lane;
    const int s   = col & 3;

    const float r00 = c_t0r[s][0], r01 = c_t0r[s][1], r02 = c_t0r[s][2];
    const float r10 = c_t1r[s][0], r11 = c_t1r[s][1], r12 = c_t1r[s][2];

    const int lb  = (lane >> 2) << 1;
    const int s00 = lb + c_off[0][s][0] + 3;
    const int s01 = lb + c_off[0][s][1] + 3;
    const int s02 = lb + c_off[0][s][2] + 3;
    const int s10 = lb + c_off[1][s][0] + 3;
    const int s11 = lb + c_off[1][s][1] + 3;
    const int s12 = lb + c_off[1][s][2] + 3;

    const int   x  = rf128(16 * wq - 3 + lane);  // staged input column
    const bool  p  = (x & 1) != 0;               // c2q column parity

    const float* ylx = ylg + x;
    const float* Rb  = yhr + (x >> 1);
    const float* Ib  = yhi + (x >> 1);

    // ---- compute one row PAIR (logical rows 2h, 2h+1) of y1, y2 ------------
    auto cpair = [&](int h, float& y1a, float& y2a, float& y1b, float& y2b) {
        const int yr0 = rf128(2 * h);
        const int yr1 = rf128(2 * h + 1);
        const int hb  = (yr0 >> 1) * HH2;

        const float yl0 = ylx[yr0 * IW] * SQ2;
        const float yl1 = ylx[yr1 * IW] * SQ2;

        const float* R = Rb + hb;
        const float* I = Ib + hb;
        const float R0  = R[0],      R5  = R[5*PL];
        const float R2v = R[2*PL],   R3v = R[3*PL];
        const float R1v = R[1*PL],   R4v = R[4*PL];
        const float I0  = I[0],      I5  = I[5*PL];
        const float I2v = I[2*PL],   I3v = I[3*PL];
        const float I1v = I[1*PL],   I4v = I[4*PL];

        // c2q (unscaled; RS2 folded into taps):
        //   A (even row): p ? Ic1+Ic2 : Rc1+Rc2
        //   B (odd  row): p ? Rc2-Rc1 : Ic1-Ic2
        float lhA = p ? (I0  + I5 ) : (R0  + R5 );
        float lhB = p ? (R5  - R0 ) : (I0  - I5 );
        float hlA = p ? (I2v + I3v) : (R2v + R3v);
        float hlB = p ? (R3v - R2v) : (I2v - I3v);
        float hhA = p ? (I1v + I4v) : (R1v + R4v);
        float hhB = p ? (R4v - R1v) : (I1v - I4v);

        if (yr0 & 1) {   // boundary reflection flips pair parity (warp-uniform)
            float t;
            t = lhA; lhA = lhB; lhB = t;
            t = hlA; hlA = hlB; hlB = t;
            t = hhA; hhA = hhB; hhB = t;
        }

        y1a = r00 * __shfl_sync(FULLM, yl0, s00)
            + r01 * __shfl_sync(FULLM, yl0, s01)
            + r02 * __shfl_sync(FULLM, yl0, s02)
            + r10 * __shfl_sync(FULLM, hlA, s10)
            + r11 * __shfl_sync(FULLM, hlA, s11)
            + r12 * __shfl_sync(FULLM, hlA, s12);
        y2a = r00 * __shfl_sync(FULLM, lhA, s00)
            + r01 * __shfl_sync(FULLM, lhA, s01)
            + r02 * __shfl_sync(FULLM, lhA, s02)
            + r10 * __shfl_sync(FULLM, hhA, s10)
            + r11 * __shfl_sync(FULLM, hhA, s11)
            + r12 * __shfl_sync(FULLM, hhA, s12);
        y1b = r00 * __shfl_sync(FULLM, yl1, s00)
            + r01 * __shfl_sync(FULLM, yl1, s01)
            + r02 * __shfl_sync(FULLM, yl1, s02)
            + r10 * __shfl_sync(FULLM, hlB, s10)
            + r11 * __shfl_sync(FULLM, hlB, s11)
            + r12 * __shfl_sync(FULLM, hlB, s12);
        y2b = r00 * __shfl_sync(FULLM, lhB, s00)
            + r01 * __shfl_sync(FULLM, lhB, s01)
            + r02 * __shfl_sync(FULLM, lhB, s02)
            + r10 * __shfl_sync(FULLM, hhB, s10)
            + r11 * __shfl_sync(FULLM, hhB, s11)
            + r12 * __shfl_sync(FULLM, hhB, s12);
    };

    // ---- vertical streaming window: w[j] = y row (2i - 4 + j), j = 0..9 ----
    float w1[10], w2[10];
#pragma unroll
    for (int k = 0; k < 5; ++k)
        cpair(k - 2, w1[2*k], w2[2*k], w1[2*k+1], w2[2*k+1]);

    float* op = og + col;
#pragma unroll 2
    for (int ii = 0; ii < 64; ++ii) {
        const float v0 = A0  * w1[8] + A2  * w1[6] + A4 * w1[4]
                       + A7  * w2[7] + A5  * w2[5] + A3c * w2[3];
        const float v1 = A7  * w1[7] + A5  * w1[5] + A3c * w1[3]
                       - A0  * w2[8] - A2  * w2[6] - A4 * w2[4];
        const float v2 = A3c * w1[6] + A5  * w1[4] + A7 * w1[2]
                       - A4  * w2[5] - A2  * w2[3] - A0 * w2[1];
        const float v3 = A4  * w1[5] + A2  * w1[3] + A0 * w1[1]
                       + A3c * w2[6] + A5  * w2[4] + A7 * w2[2];

        __stcs(op + 0 * OW, v0);
        __stcs(op + 1 * OW, v1);
        __stcs(op + 2 * OW, v2);
        __stcs(op + 3 * OW, v3);
        op += 4 * OW;

        if (ii < 63) {
#pragma unroll
            for (int j = 0; j < 8; ++j) { w1[j] = w1[j + 2]; w2[j] = w2[j + 2]; }
            cpair(ii + 3, w1[8], w2[8], w1[9], w2[9]);
        }
    }
}

extern "C" void kernel_launch(void* const* d_in, const int* in_sizes, int n_in,
                              void* d_out, int out_size)
{
    const float* Yl  = (const float*)d_in[0];
    const float* Yhr = (const float*)d_in[1];
    const float* Yhi = (const float*)d_in[2];
    float* out = (float*)d_out;

    const int n_img = in_sizes[0] / (IW * IW);   // 512 for (8,64,128,128)

    dim3 grid(2, n_img);   // x: col half (128 cols), y: image
    dtcwt_inv_kernel<<<grid, 128>>>(Yl, Yhr, Yhi, out);
}